// round 1
// baseline (speedup 1.0000x reference)
#include <cuda_runtime.h>
#include <math.h>

#define B 128
#define T_STEPS 200
#define NH 2048
#define NI 32
#define PORT 1024
#define DT 0.042f
#define THRESH 0.5f

#define SPLITK 8
#define KSPLIT (NH / SPLITK)   // 256
#define KC 16
#define NTILE 128
#define NTILES (NH / NTILE)    // 16

// ---------------- device scratch (static allocation: allowed) ----------------
__device__ float g_xin[(size_t)T_STEPS * B * NH];   // [t*B+b][n] : x @ x2h, precomputed
__device__ float g_hyT[2][(size_t)NH * B];          // hy state, transposed [n][b], ping-pong
__device__ float g_hz[(size_t)B * PORT];            // hz state [b][j]
__device__ float g_part[(size_t)SPLITK * B * NH];   // split-K partials [kb][b][n]
__device__ int   g_cnt[NTILES];                     // split-K arrival counters (self-resetting)

// ---------------- init: zero the recurrent state -----------------------------
__global__ void init_kernel() {
    int i = blockIdx.x * blockDim.x + threadIdx.x;
    if (i < NH * B)  g_hyT[0][i] = 0.0f;
    if (i < B * PORT) g_hz[i]    = 0.0f;
}

// ---------------- xin = x @ x2h for all timesteps ----------------------------
// grid: (400 row-tiles of 64, 8 n-tiles of 256), block 256.
// row index R = t*B + b ; x element = x[(b*T + t)*NI + i]
__global__ void xin_kernel(const float* __restrict__ x, const float* __restrict__ x2h) {
    __shared__ float sx[64][NI];
    const int tid = threadIdx.x;
    const int r0  = blockIdx.x * 64;
    const int n   = blockIdx.y * 256 + tid;

    for (int s = tid; s < 64 * NI; s += 256) {
        int r = s >> 5, i = s & 31;
        int R = r0 + r;
        int tt = R >> 7;        // R / 128
        int bb = R & 127;       // R % 128
        sx[r][i] = x[((size_t)bb * T_STEPS + tt) * NI + i];
    }
    __syncthreads();

    float acc[64];
#pragma unroll
    for (int r = 0; r < 64; r++) acc[r] = 0.0f;

#pragma unroll
    for (int i = 0; i < NI; i++) {
        float w = x2h[(size_t)i * NH + n];
#pragma unroll
        for (int r = 0; r < 64; r++) acc[r] = fmaf(sx[r][i], w, acc[r]);
    }
#pragma unroll
    for (int r = 0; r < 64; r++)
        g_xin[(size_t)(r0 + r) * NH + n] = acc[r];
}

// ---------------- one recurrent step: GEMM (split-K) + fused epilogue --------
// grid: (NTILES=16, SPLITK=8), block 256 (16x16), thread tile 8x8 -> CTA tile 128x128
__global__ void __launch_bounds__(256) step_kernel(
    const float* __restrict__ h2h, const float* __restrict__ gamma,
    const float* __restrict__ eps, float* __restrict__ out,
    int t, int src)
{
    const int dst = src ^ 1;
    __shared__ float shA[2][KC * B];      // hy^T chunk: [k][b]
    __shared__ float shB[2][KC * NTILE];  // h2h chunk:  [k][n]
    __shared__ int s_last;

    const int tid = threadIdx.x;
    const int tx = tid & 15, ty = tid >> 4;
    const int ntile = blockIdx.x, kb = blockIdx.y;
    const float* __restrict__ A = g_hyT[src];
    const int k0 = kb * KSPLIT;
    const int nbase0 = ntile * NTILE;

    float acc[8][8];
#pragma unroll
    for (int i = 0; i < 8; i++)
#pragma unroll
        for (int j = 0; j < 8; j++) acc[i][j] = 0.0f;

    float4 ra[2], rb[2];

    // --- stage chunk 0 ---
    {
        const float4* pA = (const float4*)&A[(size_t)k0 * B];
        ra[0] = pA[tid]; ra[1] = pA[tid + 256];
#pragma unroll
        for (int s = 0; s < 2; s++) {
            int idx = tid + s * 256;
            int row = idx >> 5, c4 = idx & 31;
            rb[s] = *(const float4*)&h2h[(size_t)(k0 + row) * NH + nbase0 + c4 * 4];
        }
        float4* qA = (float4*)&shA[0][0];
        qA[tid] = ra[0]; qA[tid + 256] = ra[1];
#pragma unroll
        for (int s = 0; s < 2; s++) {
            int idx = tid + s * 256;
            int row = idx >> 5, c4 = idx & 31;
            *(float4*)&shB[0][row * NTILE + c4 * 4] = rb[s];
        }
    }
    __syncthreads();

    const int NCH = KSPLIT / KC;   // 16
    int buf = 0;
    for (int c = 0; c < NCH; c++) {
        if (c + 1 < NCH) {
            int kc = k0 + (c + 1) * KC;
            const float4* pA = (const float4*)&A[(size_t)kc * B];
            ra[0] = pA[tid]; ra[1] = pA[tid + 256];
#pragma unroll
            for (int s = 0; s < 2; s++) {
                int idx = tid + s * 256;
                int row = idx >> 5, c4 = idx & 31;
                rb[s] = *(const float4*)&h2h[(size_t)(kc + row) * NH + nbase0 + c4 * 4];
            }
        }
#pragma unroll
        for (int kk = 0; kk < KC; kk++) {
            float4 a0 = *(const float4*)&shA[buf][kk * B + ty * 8];
            float4 a1 = *(const float4*)&shA[buf][kk * B + ty * 8 + 4];
            float4 b0 = *(const float4*)&shB[buf][kk * NTILE + tx * 8];
            float4 b1 = *(const float4*)&shB[buf][kk * NTILE + tx * 8 + 4];
            float av[8] = {a0.x, a0.y, a0.z, a0.w, a1.x, a1.y, a1.z, a1.w};
            float bv[8] = {b0.x, b0.y, b0.z, b0.w, b1.x, b1.y, b1.z, b1.w};
#pragma unroll
            for (int i = 0; i < 8; i++)
#pragma unroll
                for (int j = 0; j < 8; j++)
                    acc[i][j] = fmaf(av[i], bv[j], acc[i][j]);
        }
        if (c + 1 < NCH) {
            float4* qA = (float4*)&shA[buf ^ 1][0];
            qA[tid] = ra[0]; qA[tid + 256] = ra[1];
#pragma unroll
            for (int s = 0; s < 2; s++) {
                int idx = tid + s * 256;
                int row = idx >> 5, c4 = idx & 31;
                *(float4*)&shB[buf ^ 1][row * NTILE + c4 * 4] = rb[s];
            }
        }
        __syncthreads();
        buf ^= 1;
    }

    // --- write split-K partials ---
#pragma unroll
    for (int i = 0; i < 8; i++) {
        int b = ty * 8 + i;
        float4 v0 = make_float4(acc[i][0], acc[i][1], acc[i][2], acc[i][3]);
        float4 v1 = make_float4(acc[i][4], acc[i][5], acc[i][6], acc[i][7]);
        float4* p = (float4*)&g_part[((size_t)kb * B + b) * NH + nbase0 + tx * 8];
        p[0] = v0; p[1] = v1;
    }
    __threadfence();
    if (tid == 0) {
        int v = atomicAdd(&g_cnt[ntile], 1);
        s_last = (v == SPLITK - 1);
    }
    __syncthreads();
    if (!s_last) return;
    if (tid == 0) g_cnt[ntile] = 0;   // self-reset for next launch

    // --- fused epilogue (last CTA of this n-tile) ---
    // remap: warp -> batch row, lane -> 4 consecutive n (coalesced HBM writes)
    const int warp = tid >> 5, lane = tid & 31;
    const int n4 = nbase0 + lane * 4;
    const bool harm = (nbase0 < PORT);

    float4 gm = make_float4(0, 0, 0, 0), ep = make_float4(0, 0, 0, 0);
    if (harm) {
        gm = *(const float4*)&gamma[n4];
        ep = *(const float4*)&eps[n4];
    }

    float* out_hy  = out;
    float* out_hz  = out + (size_t)T_STEPS * B * NH;
    float* out_hyu = out_hz + (size_t)T_STEPS * B * PORT;
    float* out_spk = out_hyu + (size_t)T_STEPS * B * PORT;
    float* hyT_dst = g_hyT[dst];

    for (int r = 0; r < 16; r++) {
        int b = r * 8 + warp;
        float4 pre = make_float4(0, 0, 0, 0);
#pragma unroll
        for (int q = 0; q < SPLITK; q++) {
            float4 pv = *(const float4*)&g_part[((size_t)q * B + b) * NH + n4];
            pre.x += pv.x; pre.y += pv.y; pre.z += pv.z; pre.w += pv.w;
        }
        float4 xv = *(const float4*)&g_xin[((size_t)t * B + b) * NH + n4];
        pre.x += xv.x; pre.y += xv.y; pre.z += xv.z; pre.w += xv.w;

        float4 f;
        f.x = tanhf(pre.x); f.y = tanhf(pre.y);
        f.z = tanhf(pre.z); f.w = tanhf(pre.w);

        const size_t ob = (size_t)t * B + b;

        if (harm) {
            float4 hyo, hzo, hzn, hym;
            hyo.x = A[(size_t)(n4 + 0) * B + b];
            hyo.y = A[(size_t)(n4 + 1) * B + b];
            hyo.z = A[(size_t)(n4 + 2) * B + b];
            hyo.w = A[(size_t)(n4 + 3) * B + b];
            hzo = *(const float4*)&g_hz[(size_t)b * PORT + n4];

            hzn.x = hzo.x + DT * (f.x - gm.x * hyo.x - ep.x * hzo.x);
            hzn.y = hzo.y + DT * (f.y - gm.y * hyo.y - ep.y * hzo.y);
            hzn.z = hzo.z + DT * (f.z - gm.z * hyo.z - ep.z * hzo.z);
            hzn.w = hzo.w + DT * (f.w - gm.w * hyo.w - ep.w * hzo.w);
            hym.x = hyo.x + DT * hzn.x;
            hym.y = hyo.y + DT * hzn.y;
            hym.z = hyo.z + DT * hzn.z;
            hym.w = hyo.w + DT * hzn.w;

            *(float4*)&out_hy[ob * NH + n4]  = hym;
            *(float4*)&out_hz[ob * PORT + n4] = hzn;
            *(float4*)&g_hz[(size_t)b * PORT + n4] = hzn;
            hyT_dst[(size_t)(n4 + 0) * B + b] = hym.x;
            hyT_dst[(size_t)(n4 + 1) * B + b] = hym.y;
            hyT_dst[(size_t)(n4 + 2) * B + b] = hym.z;
            hyT_dst[(size_t)(n4 + 3) * B + b] = hym.w;
        } else {
            int j4 = n4 - PORT;
            float4 u, spk, hyu;
            u.x = A[(size_t)(n4 + 0) * B + b];
            u.y = A[(size_t)(n4 + 1) * B + b];
            u.z = A[(size_t)(n4 + 2) * B + b];
            u.w = A[(size_t)(n4 + 3) * B + b];

            spk.x = (u.x > THRESH) ? 1.0f : 0.0f;
            spk.y = (u.y > THRESH) ? 1.0f : 0.0f;
            spk.z = (u.z > THRESH) ? 1.0f : 0.0f;
            spk.w = (u.w > THRESH) ? 1.0f : 0.0f;
            float urx = (spk.x > 0.0f) ? 0.0f : u.x;
            float ury = (spk.y > 0.0f) ? 0.0f : u.y;
            float urz = (spk.z > 0.0f) ? 0.0f : u.z;
            float urw = (spk.w > 0.0f) ? 0.0f : u.w;
            hyu.x = urx + DT * (f.x - urx);
            hyu.y = ury + DT * (f.y - ury);
            hyu.z = urz + DT * (f.z - urz);
            hyu.w = urw + DT * (f.w - urw);

            *(float4*)&out_hy[ob * NH + n4]    = hyu;
            *(float4*)&out_hyu[ob * PORT + j4] = hyu;
            *(float4*)&out_spk[ob * PORT + j4] = spk;
            hyT_dst[(size_t)(n4 + 0) * B + b] = hyu.x;
            hyT_dst[(size_t)(n4 + 1) * B + b] = hyu.y;
            hyT_dst[(size_t)(n4 + 2) * B + b] = hyu.z;
            hyT_dst[(size_t)(n4 + 3) * B + b] = hyu.w;
        }
    }
}

// ---------------- launch ------------------------------------------------------
extern "C" void kernel_launch(void* const* d_in, const int* in_sizes, int n_in,
                              void* d_out, int out_size) {
    const float* x     = (const float*)d_in[0];   // [B, T, NI]
    const float* x2h   = (const float*)d_in[1];   // [NI, NH]
    const float* h2h   = (const float*)d_in[2];   // [NH, NH]
    const float* gamma = (const float*)d_in[3];   // [NH]
    const float* eps   = (const float*)d_in[4];   // [NH]
    float* out = (float*)d_out;

    init_kernel<<<256, 1024>>>();
    xin_kernel<<<dim3((T_STEPS * B) / 64, NH / 256), 256>>>(x, x2h);
    for (int t = 0; t < T_STEPS; t++)
        step_kernel<<<dim3(NTILES, SPLITK), 256>>>(h2h, gamma, eps, out, t, t & 1);
}

// round 2
// speedup vs baseline: 1.1031x; 1.1031x over previous
#include <cuda_runtime.h>
#include <math.h>

#define B 128
#define T_STEPS 200
#define NH 2048
#define NI 32
#define PORT 1024
#define DT 0.042f
#define THRESH 0.5f

#define SPLITK 16
#define KSLICE (NH / SPLITK)   // 128
#define KC 16
#define MT 64
#define NT 128
#define NTILES (NH / NT)       // 16
#define MTILES (B / MT)        // 2

// ---------------- device scratch ----------------
__device__ float g_xin[(size_t)T_STEPS * B * NH];   // x @ x2h precomputed, [t*B+b][n]
__device__ float g_hyT[2][(size_t)NH * B];          // hy transposed [n][b], ping-pong (GEMM A)
__device__ float g_hz[(size_t)B * PORT];            // hz state [b][j]
__device__ float g_part[(size_t)SPLITK * B * NH];   // split-K partials [kb][b][n]
__device__ int   g_cnt[NTILES * MTILES];            // arrival counters (self-resetting)

__global__ void init_kernel() {
    int i = blockIdx.x * blockDim.x + threadIdx.x;
    if (i < NH * B)   g_hyT[0][i] = 0.0f;
    if (i < B * PORT) g_hz[i]     = 0.0f;
}

// ---------------- xin = x @ x2h for all timesteps ----------------------------
__global__ void xin_kernel(const float* __restrict__ x, const float* __restrict__ x2h) {
    __shared__ float sx[64][NI];
    const int tid = threadIdx.x;
    const int r0  = blockIdx.x * 64;
    const int n   = blockIdx.y * 256 + tid;

    for (int s = tid; s < 64 * NI; s += 256) {
        int r = s >> 5, i = s & 31;
        int R = r0 + r;
        int tt = R >> 7, bb = R & 127;
        sx[r][i] = x[((size_t)bb * T_STEPS + tt) * NI + i];
    }
    __syncthreads();

    float acc[64];
#pragma unroll
    for (int r = 0; r < 64; r++) acc[r] = 0.0f;
#pragma unroll
    for (int i = 0; i < NI; i++) {
        float w = x2h[(size_t)i * NH + n];
#pragma unroll
        for (int r = 0; r < 64; r++) acc[r] = fmaf(sx[r][i], w, acc[r]);
    }
#pragma unroll
    for (int r = 0; r < 64; r++)
        g_xin[(size_t)(r0 + r) * NH + n] = acc[r];
}

// ---------------- one recurrent step: split-K GEMM + fused epilogue ----------
// grid (NTILES, MTILES, SPLITK), block 128. CTA tile 64(M) x 128(N), thread 8x8.
__global__ void __launch_bounds__(128, 4) step_kernel(
    const float* __restrict__ h2h, const float* __restrict__ gamma,
    const float* __restrict__ eps, float* __restrict__ out,
    int t, int src)
{
    const int dst = src ^ 1;
    // smem pool: GEMM uses 6144 floats (shA 2x1024 + shB 2x2048); epilogue reuses
    // the pool as sNew[128][65] (8320 floats).
    __shared__ float pool[128 * 65];
    __shared__ int s_last;
    float* shA = pool;           // [2][KC*MT]
    float* shB = pool + 2048;    // [2][KC*NT]

    const int tid = threadIdx.x;
    const int tx = tid & 15, ty = tid >> 4;
    const int ntile = blockIdx.x, mtile = blockIdx.y, kb = blockIdx.z;
    const int n0 = ntile * NT, m0 = mtile * MT;
    const int k0 = kb * KSLICE;
    const float* __restrict__ A = g_hyT[src];

    float acc[8][8];
#pragma unroll
    for (int i = 0; i < 8; i++)
#pragma unroll
        for (int j = 0; j < 8; j++) acc[i][j] = 0.0f;

    float4 ra[2], rb[4];

    // stage chunk 0
    {
#pragma unroll
        for (int s = 0; s < 2; s++) {
            int idx = tid + s * 128;
            int row = idx >> 4, c4 = idx & 15;
            ra[s] = *(const float4*)&A[(size_t)(k0 + row) * B + m0 + c4 * 4];
        }
#pragma unroll
        for (int s = 0; s < 4; s++) {
            int idx = tid + s * 128;
            int row = idx >> 5, c4 = idx & 31;
            rb[s] = *(const float4*)&h2h[(size_t)(k0 + row) * NH + n0 + c4 * 4];
        }
#pragma unroll
        for (int s = 0; s < 2; s++) {
            int idx = tid + s * 128;
            int row = idx >> 4, c4 = idx & 15;
            *(float4*)&shA[row * MT + c4 * 4] = ra[s];
        }
#pragma unroll
        for (int s = 0; s < 4; s++) {
            int idx = tid + s * 128;
            int row = idx >> 5, c4 = idx & 31;
            *(float4*)&shB[row * NT + c4 * 4] = rb[s];
        }
    }
    __syncthreads();

    const int NCH = KSLICE / KC;   // 8
    int buf = 0;
    for (int c = 0; c < NCH; c++) {
        if (c + 1 < NCH) {
            int kc = k0 + (c + 1) * KC;
#pragma unroll
            for (int s = 0; s < 2; s++) {
                int idx = tid + s * 128;
                int row = idx >> 4, c4 = idx & 15;
                ra[s] = *(const float4*)&A[(size_t)(kc + row) * B + m0 + c4 * 4];
            }
#pragma unroll
            for (int s = 0; s < 4; s++) {
                int idx = tid + s * 128;
                int row = idx >> 5, c4 = idx & 31;
                rb[s] = *(const float4*)&h2h[(size_t)(kc + row) * NH + n0 + c4 * 4];
            }
        }
        const float* sA = shA + buf * (KC * MT);
        const float* sB = shB + buf * (KC * NT);
#pragma unroll
        for (int kk = 0; kk < KC; kk++) {
            float4 a0 = *(const float4*)&sA[kk * MT + ty * 8];
            float4 a1 = *(const float4*)&sA[kk * MT + ty * 8 + 4];
            float4 b0 = *(const float4*)&sB[kk * NT + tx * 8];
            float4 b1 = *(const float4*)&sB[kk * NT + tx * 8 + 4];
            float av[8] = {a0.x, a0.y, a0.z, a0.w, a1.x, a1.y, a1.z, a1.w};
            float bv[8] = {b0.x, b0.y, b0.z, b0.w, b1.x, b1.y, b1.z, b1.w};
#pragma unroll
            for (int i = 0; i < 8; i++)
#pragma unroll
                for (int j = 0; j < 8; j++)
                    acc[i][j] = fmaf(av[i], bv[j], acc[i][j]);
        }
        if (c + 1 < NCH) {
            float* dA = shA + (buf ^ 1) * (KC * MT);
            float* dB = shB + (buf ^ 1) * (KC * NT);
#pragma unroll
            for (int s = 0; s < 2; s++) {
                int idx = tid + s * 128;
                int row = idx >> 4, c4 = idx & 15;
                *(float4*)&dA[row * MT + c4 * 4] = ra[s];
            }
#pragma unroll
            for (int s = 0; s < 4; s++) {
                int idx = tid + s * 128;
                int row = idx >> 5, c4 = idx & 31;
                *(float4*)&dB[row * NT + c4 * 4] = rb[s];
            }
        }
        __syncthreads();
        buf ^= 1;
    }

    // write split-K partials
#pragma unroll
    for (int i = 0; i < 8; i++) {
        int b = m0 + ty * 8 + i;
        float4 v0 = make_float4(acc[i][0], acc[i][1], acc[i][2], acc[i][3]);
        float4 v1 = make_float4(acc[i][4], acc[i][5], acc[i][6], acc[i][7]);
        float4* p = (float4*)&g_part[((size_t)kb * B + b) * NH + n0 + tx * 8];
        p[0] = v0; p[1] = v1;
    }
    __threadfence();
    if (tid == 0) {
        int v = atomicAdd(&g_cnt[ntile * MTILES + mtile], 1);
        s_last = (v == SPLITK - 1);
    }
    __syncthreads();
    if (!s_last) return;
    if (tid == 0) g_cnt[ntile * MTILES + mtile] = 0;

    // ---------------- fused epilogue (last CTA of this (m,n) tile) -----------
    float (*sNew)[65] = (float(*)[65])pool;   // safe: all smem reads done

    const int w = tid >> 5, l = tid & 31;
    const bool harm = (n0 < PORT);

    float* out_hy  = out;
    float* out_hz  = out + (size_t)T_STEPS * B * NH;
    float* out_hyu = out_hz + (size_t)T_STEPS * B * PORT;
    float* out_spk = out_hyu + (size_t)T_STEPS * B * PORT;
    float* hyT_dst = g_hyT[dst];
    const float* old_hy = out_hy + (size_t)(t - 1) * B * NH;   // valid for t>=1

    for (int r = 0; r < 16; r++) {
        int bl = r * 4 + w;
        int b  = m0 + bl;
        const size_t ob = (size_t)t * B + b;
#pragma unroll
        for (int j = 0; j < 4; j++) {
            int nl = j * 32 + l;
            int n  = n0 + nl;

            float pre = 0.0f;
#pragma unroll
            for (int q = 0; q < SPLITK; q++)
                pre += g_part[((size_t)q * B + b) * NH + n];
            pre += g_xin[((size_t)t * B + b) * NH + n];
            float f = tanhf(pre);

            float old = (t == 0) ? 0.0f : old_hy[(size_t)b * NH + n];

            float newv;
            if (harm) {
                float hzo = g_hz[(size_t)b * PORT + n];
                float hzn = hzo + DT * (f - gamma[n] * old - eps[n] * hzo);
                newv = old + DT * hzn;
                out_hy[ob * NH + n]          = newv;
                out_hz[ob * PORT + n]        = hzn;
                g_hz[(size_t)b * PORT + n]   = hzn;
            } else {
                int j4 = n - PORT;
                float spk = (old > THRESH) ? 1.0f : 0.0f;
                float u   = (spk > 0.0f) ? 0.0f : old;
                newv = u + DT * (f - u);
                out_hy[ob * NH + n]     = newv;
                out_hyu[ob * PORT + j4] = newv;
                out_spk[ob * PORT + j4] = spk;
            }
            sNew[nl][bl] = newv;
        }
    }
    __syncthreads();

    // coalesced transposed-state writeback for next step's GEMM
#pragma unroll 8
    for (int i = 0; i < 64; i++) {
        int idx = tid + i * 128;
        int row = idx >> 6, col = idx & 63;
        hyT_dst[(size_t)(n0 + row) * B + m0 + col] = sNew[row][col];
    }
}

// ---------------- launch ------------------------------------------------------
extern "C" void kernel_launch(void* const* d_in, const int* in_sizes, int n_in,
                              void* d_out, int out_size) {
    const float* x     = (const float*)d_in[0];
    const float* x2h   = (const float*)d_in[1];
    const float* h2h   = (const float*)d_in[2];
    const float* gamma = (const float*)d_in[3];
    const float* eps   = (const float*)d_in[4];
    float* out = (float*)d_out;

    init_kernel<<<256, 1024>>>();
    xin_kernel<<<dim3((T_STEPS * B) / 64, NH / 256), 256>>>(x, x2h);
    for (int t = 0; t < T_STEPS; t++)
        step_kernel<<<dim3(NTILES, MTILES, SPLITK), 128>>>(h2h, gamma, eps, out, t, t & 1);
}

// round 4
// speedup vs baseline: 2.3587x; 2.1384x over previous
#include <cuda_runtime.h>
#include <math.h>
#include <stdint.h>

#define B 128
#define T_STEPS 200
#define NH 2048
#define NI 32
#define PORT 1024
#define DT 0.042f
#define THRESH 0.5f

#define SPLITK 8
#define KSLICE 256            // K per CTA
#define KC 32                 // K per smem stage
#define NT 128
#define NTILES 16
#define TSTRIDE 36            // padded floats per smem tile row (conflict-free)
#define TSZ (128 * TSTRIDE)   // floats per tile
#define SMEM_BYTES (8 * TSZ * 4)   // 4 tiles x 2 buffers = 147456 B

// ---------------- device scratch ----------------
__device__ float g_xin[(size_t)T_STEPS * B * NH];   // x @ x2h, [t*B+b][n]
__device__ float g_Whi[(size_t)NH * NH];            // h2h^T tf32-hi, [n][k]
__device__ float g_Wlo[(size_t)NH * NH];            // h2h^T tf32-lo, [n][k]
__device__ float g_Ahi[2][(size_t)B * NH];          // hy tf32-hi, [b][k], ping-pong
__device__ float g_Alo[2][(size_t)B * NH];          // hy tf32-lo
__device__ float g_hz[(size_t)B * PORT];            // hz state [b][j]
__device__ float g_part[(size_t)SPLITK * B * NH];   // split-K partials [kb][b][n]
__device__ int   g_cnt[NTILES];                     // arrival counters (self-reset)

// ---------------- helpers ----------------
__device__ __forceinline__ uint32_t smem_u32(const void* p) {
    uint32_t a;
    asm("{ .reg .u64 t; cvta.to.shared.u64 t, %1; cvt.u32.u64 %0, t; }" : "=r"(a) : "l"(p));
    return a;
}
__device__ __forceinline__ float tf32r(float x) {
    uint32_t u;
    asm("cvt.rna.tf32.f32 %0, %1;" : "=r"(u) : "f"(x));
    return __uint_as_float(u);
}
__device__ __forceinline__ void cpa16(uint32_t dst, const void* src) {
    asm volatile("cp.async.ca.shared.global [%0], [%1], 16;" :: "r"(dst), "l"(src));
}
#define CP_COMMIT() asm volatile("cp.async.commit_group;" ::: "memory")
#define CP_WAIT(n)  asm volatile("cp.async.wait_group %0;" :: "n"(n) : "memory")

__device__ __forceinline__ void mma_tf32(float* c, const uint32_t* a, const uint32_t* b) {
    asm volatile(
        "mma.sync.aligned.m16n8k8.row.col.f32.tf32.tf32.f32 "
        "{%0,%1,%2,%3}, {%4,%5,%6,%7}, {%8,%9}, {%0,%1,%2,%3};"
        : "+f"(c[0]), "+f"(c[1]), "+f"(c[2]), "+f"(c[3])
        : "r"(a[0]), "r"(a[1]), "r"(a[2]), "r"(a[3]), "r"(b[0]), "r"(b[1]));
}

// ---------------- init ----------------
__global__ void init_kernel() {
    int i = blockIdx.x * blockDim.x + threadIdx.x;
    if (i < B * NH) { g_Ahi[0][i] = 0.0f; g_Alo[0][i] = 0.0f; }
    if (i < B * PORT) g_hz[i] = 0.0f;
}

// ---------------- h2h -> transposed tf32 hi/lo split (one-time) --------------
__global__ void prep_kernel(const float* __restrict__ h2h) {
    __shared__ float s[32][33];
    int k = blockIdx.y * 32 + threadIdx.y;
    int n = blockIdx.x * 32 + threadIdx.x;
    s[threadIdx.y][threadIdx.x] = h2h[(size_t)k * NH + n];
    __syncthreads();
    int n2 = blockIdx.x * 32 + threadIdx.y;
    int k2 = blockIdx.y * 32 + threadIdx.x;
    float v = s[threadIdx.x][threadIdx.y];
    float hi = tf32r(v);
    g_Whi[(size_t)n2 * NH + k2] = hi;
    g_Wlo[(size_t)n2 * NH + k2] = tf32r(v - hi);
}

// ---------------- xin = x @ x2h for all timesteps (one-time) -----------------
__global__ void xin_kernel(const float* __restrict__ x, const float* __restrict__ x2h) {
    __shared__ float sx[64][NI];
    const int tid = threadIdx.x;
    const int r0 = blockIdx.x * 64;
    const int n = blockIdx.y * 256 + tid;
    for (int s = tid; s < 64 * NI; s += 256) {
        int r = s >> 5, i = s & 31;
        int R = r0 + r;
        int tt = R >> 7, bb = R & 127;
        sx[r][i] = x[((size_t)bb * T_STEPS + tt) * NI + i];
    }
    __syncthreads();
    float acc[64];
#pragma unroll
    for (int r = 0; r < 64; r++) acc[r] = 0.0f;
#pragma unroll
    for (int i = 0; i < NI; i++) {
        float w = x2h[(size_t)i * NH + n];
#pragma unroll
        for (int r = 0; r < 64; r++) acc[r] = fmaf(sx[r][i], w, acc[r]);
    }
#pragma unroll
    for (int r = 0; r < 64; r++)
        g_xin[(size_t)(r0 + r) * NH + n] = acc[r];
}

// ---------------- one step: tf32 mma.sync split GEMM + fused epilogue --------
__global__ void __launch_bounds__(256, 1) step_kernel(
    const float* __restrict__ gamma, const float* __restrict__ eps,
    float* __restrict__ out, int t, int src)
{
    extern __shared__ float sm[];
    __shared__ int s_last;

    const int tid = threadIdx.x;
    const int warp = tid >> 5, lane = tid & 31;
    const int warpM = warp >> 2, warpN = warp & 3;   // 2 x 4 warp grid
    const int ntile = blockIdx.x, kb = blockIdx.y;
    const int n0 = ntile * NT, k0 = kb * KSLICE;
    const int dst = src ^ 1;

    const float* __restrict__ Ahi = g_Ahi[src];
    const float* __restrict__ Alo = g_Alo[src];

    // tiles: 0=Ahi, 1=Alo, 2=Whi, 3=Wlo; two buffers
    const uint32_t smb = smem_u32(sm);

    // ---- cp.async stage of one K-chunk into buf (c & 1) ----
    auto issue = [&](int c) {
        float* bb = sm + (c & 1) * 4 * TSZ;
        const int kc = k0 + c * KC;
        const float* srcs[4] = {
            Ahi + kc, Alo + kc,
            g_Whi + (size_t)n0 * NH + kc, g_Wlo + (size_t)n0 * NH + kc
        };
#pragma unroll
        for (int tile = 0; tile < 4; tile++) {
            const float* sg = srcs[tile];
            float* dt = bb + tile * TSZ;
#pragma unroll
            for (int i = 0; i < 4; i++) {
                int s = tid + i * 256;          // 1024 slots: 128 rows x 8 x 16B
                int row = s >> 3, u = s & 7;
                cpa16(smem_u32(dt + row * TSTRIDE + u * 4),
                      sg + (size_t)row * NH + u * 4);
            }
        }
    };

    float C[4][4][4];
#pragma unroll
    for (int mi = 0; mi < 4; mi++)
#pragma unroll
        for (int ni = 0; ni < 4; ni++)
#pragma unroll
            for (int q = 0; q < 4; q++) C[mi][ni][q] = 0.0f;

    const int r = lane >> 2, cc = lane & 3;

    issue(0); CP_COMMIT();
    for (int c = 0; c < 8; c++) {
        if (c < 7) { issue(c + 1); CP_COMMIT(); CP_WAIT(1); }
        else       { CP_WAIT(0); }
        __syncthreads();
        const float* bb   = sm + (c & 1) * 4 * TSZ;
        const float* sAhi = bb;
        const float* sAlo = bb + TSZ;
        const float* sWhi = bb + 2 * TSZ;
        const float* sWlo = bb + 3 * TSZ;

#pragma unroll
        for (int ks = 0; ks < 4; ks++) {
            const int kk = ks * 8;
            uint32_t a[4][4], bh[4][2], bl[4][2];
#pragma unroll
            for (int mi = 0; mi < 4; mi++) {
                int row = warpM * 64 + mi * 16 + r;
                a[mi][0] = __float_as_uint(sAhi[row * TSTRIDE + kk + cc]);
                a[mi][1] = __float_as_uint(sAhi[(row + 8) * TSTRIDE + kk + cc]);
                a[mi][2] = __float_as_uint(sAhi[row * TSTRIDE + kk + cc + 4]);
                a[mi][3] = __float_as_uint(sAhi[(row + 8) * TSTRIDE + kk + cc + 4]);
            }
#pragma unroll
            for (int ni = 0; ni < 4; ni++) {
                int col = warpN * 32 + ni * 8 + r;
                bh[ni][0] = __float_as_uint(sWhi[col * TSTRIDE + kk + cc]);
                bh[ni][1] = __float_as_uint(sWhi[col * TSTRIDE + kk + cc + 4]);
                bl[ni][0] = __float_as_uint(sWlo[col * TSTRIDE + kk + cc]);
                bl[ni][1] = __float_as_uint(sWlo[col * TSTRIDE + kk + cc + 4]);
            }
#pragma unroll
            for (int mi = 0; mi < 4; mi++)
#pragma unroll
                for (int ni = 0; ni < 4; ni++) {
                    mma_tf32(C[mi][ni], a[mi], bh[ni]);   // Ahi * Whi
                    mma_tf32(C[mi][ni], a[mi], bl[ni]);   // Ahi * Wlo
                }
            // Alo pass (reuse bh)
#pragma unroll
            for (int mi = 0; mi < 4; mi++) {
                int row = warpM * 64 + mi * 16 + r;
                a[mi][0] = __float_as_uint(sAlo[row * TSTRIDE + kk + cc]);
                a[mi][1] = __float_as_uint(sAlo[(row + 8) * TSTRIDE + kk + cc]);
                a[mi][2] = __float_as_uint(sAlo[row * TSTRIDE + kk + cc + 4]);
                a[mi][3] = __float_as_uint(sAlo[(row + 8) * TSTRIDE + kk + cc + 4]);
            }
#pragma unroll
            for (int mi = 0; mi < 4; mi++)
#pragma unroll
                for (int ni = 0; ni < 4; ni++)
                    mma_tf32(C[mi][ni], a[mi], bh[ni]);   // Alo * Whi
        }
        __syncthreads();
    }

    // ---- write split-K partials ----
#pragma unroll
    for (int mi = 0; mi < 4; mi++)
#pragma unroll
        for (int ni = 0; ni < 4; ni++) {
            int row = warpM * 64 + mi * 16 + r;
            int col = n0 + warpN * 32 + ni * 8 + cc * 2;
            float2 v0 = make_float2(C[mi][ni][0], C[mi][ni][1]);
            float2 v1 = make_float2(C[mi][ni][2], C[mi][ni][3]);
            *(float2*)&g_part[((size_t)kb * B + row) * NH + col]     = v0;
            *(float2*)&g_part[((size_t)kb * B + row + 8) * NH + col] = v1;
        }

    __threadfence();
    if (tid == 0) {
        int v = atomicAdd(&g_cnt[ntile], 1);
        s_last = (v == SPLITK - 1);
    }
    __syncthreads();
    if (!s_last) return;
    if (tid == 0) g_cnt[ntile] = 0;

    // ---- fused epilogue (last CTA of this n-tile): 128 b x 128 n ------------
    const int n4 = n0 + lane * 4;
    const bool harm = (n0 < PORT);

    float4 gm = make_float4(0, 0, 0, 0), ep = make_float4(0, 0, 0, 0);
    if (harm) { gm = *(const float4*)&gamma[n4]; ep = *(const float4*)&eps[n4]; }

    float* out_hy  = out;
    float* out_hz  = out + (size_t)T_STEPS * B * NH;
    float* out_hyu = out_hz + (size_t)T_STEPS * B * PORT;
    float* out_spk = out_hyu + (size_t)T_STEPS * B * PORT;
    float* hyhi_d = g_Ahi[dst];
    float* hylo_d = g_Alo[dst];
    const float* old_hy = out_hy + (size_t)(t - 1) * B * NH;

    for (int rr = 0; rr < 16; rr++) {
        int b = rr * 8 + warp;
        const size_t ob = (size_t)t * B + b;

        float4 pre = make_float4(0, 0, 0, 0);
#pragma unroll
        for (int q = 0; q < SPLITK; q++) {
            float4 pv = *(const float4*)&g_part[((size_t)q * B + b) * NH + n4];
            pre.x += pv.x; pre.y += pv.y; pre.z += pv.z; pre.w += pv.w;
        }
        float4 xv = *(const float4*)&g_xin[((size_t)t * B + b) * NH + n4];
        pre.x += xv.x; pre.y += xv.y; pre.z += xv.z; pre.w += xv.w;

        float4 f;
        f.x = tanhf(pre.x); f.y = tanhf(pre.y);
        f.z = tanhf(pre.z); f.w = tanhf(pre.w);

        float4 old = make_float4(0, 0, 0, 0);
        if (t > 0) old = *(const float4*)&old_hy[(size_t)b * NH + n4];

        float4 newv;
        if (harm) {
            float4 hzo = *(const float4*)&g_hz[(size_t)b * PORT + n4];
            float4 hzn;
            hzn.x = hzo.x + DT * (f.x - gm.x * old.x - ep.x * hzo.x);
            hzn.y = hzo.y + DT * (f.y - gm.y * old.y - ep.y * hzo.y);
            hzn.z = hzo.z + DT * (f.z - gm.z * old.z - ep.z * hzo.z);
            hzn.w = hzo.w + DT * (f.w - gm.w * old.w - ep.w * hzo.w);
            newv.x = old.x + DT * hzn.x;
            newv.y = old.y + DT * hzn.y;
            newv.z = old.z + DT * hzn.z;
            newv.w = old.w + DT * hzn.w;
            *(float4*)&out_hy[ob * NH + n4]   = newv;
            *(float4*)&out_hz[ob * PORT + n4] = hzn;
            *(float4*)&g_hz[(size_t)b * PORT + n4] = hzn;
        } else {
            int j4 = n4 - PORT;
            float4 spk, u;
            spk.x = (old.x > THRESH) ? 1.0f : 0.0f;
            spk.y = (old.y > THRESH) ? 1.0f : 0.0f;
            spk.z = (old.z > THRESH) ? 1.0f : 0.0f;
            spk.w = (old.w > THRESH) ? 1.0f : 0.0f;
            u.x = (spk.x > 0.0f) ? 0.0f : old.x;
            u.y = (spk.y > 0.0f) ? 0.0f : old.y;
            u.z = (spk.z > 0.0f) ? 0.0f : old.z;
            u.w = (spk.w > 0.0f) ? 0.0f : old.w;
            newv.x = u.x + DT * (f.x - u.x);
            newv.y = u.y + DT * (f.y - u.y);
            newv.z = u.z + DT * (f.z - u.z);
            newv.w = u.w + DT * (f.w - u.w);
            *(float4*)&out_hy[ob * NH + n4]    = newv;
            *(float4*)&out_hyu[ob * PORT + j4] = newv;
            *(float4*)&out_spk[ob * PORT + j4] = spk;
        }
        // tf32 hi/lo split of new state for next step's GEMM (A row-major [b][k])
        float4 hi4, lo4;
        hi4.x = tf32r(newv.x); lo4.x = tf32r(newv.x - hi4.x);
        hi4.y = tf32r(newv.y); lo4.y = tf32r(newv.y - hi4.y);
        hi4.z = tf32r(newv.z); lo4.z = tf32r(newv.z - hi4.z);
        hi4.w = tf32r(newv.w); lo4.w = tf32r(newv.w - hi4.w);
        *(float4*)&hyhi_d[(size_t)b * NH + n4] = hi4;
        *(float4*)&hylo_d[(size_t)b * NH + n4] = lo4;
    }
}

// ---------------- launch ------------------------------------------------------
extern "C" void kernel_launch(void* const* d_in, const int* in_sizes, int n_in,
                              void* d_out, int out_size) {
    (void)in_sizes; (void)n_in; (void)out_size;
    const float* x     = (const float*)d_in[0];
    const float* x2h   = (const float*)d_in[1];
    const float* h2h   = (const float*)d_in[2];
    const float* gamma = (const float*)d_in[3];
    const float* eps   = (const float*)d_in[4];
    float* out = (float*)d_out;

    cudaFuncSetAttribute(step_kernel, cudaFuncAttributeMaxDynamicSharedMemorySize, SMEM_BYTES);

    init_kernel<<<256, 1024>>>();
    prep_kernel<<<dim3(NH / 32, NH / 32), dim3(32, 32)>>>(h2h);
    xin_kernel<<<dim3((T_STEPS * B) / 64, NH / 256), 256>>>(x, x2h);
    for (int t = 0; t < T_STEPS; t++)
        step_kernel<<<dim3(NTILES, SPLITK), 256, SMEM_BYTES>>>(gamma, eps, out, t, t & 1);
}

// round 5
// speedup vs baseline: 2.6819x; 1.1370x over previous
#include <cuda_runtime.h>
#include <math.h>
#include <stdint.h>

#define B 128
#define T_STEPS 200
#define NH 2048
#define NI 32
#define PORT 1024
#define DT 0.042f
#define THRESH 0.5f

#define SPLITK 8
#define KSLICE 256            // K per CTA
#define KC 32                 // K per smem stage
#define NT 128
#define NTILES 16
#define TSTRIDE 36            // padded floats per smem tile row (conflict-free)
#define TSZ (128 * TSTRIDE)   // floats per tile
#define SMEM_BYTES (8 * TSZ * 4)   // 4 tiles x 2 buffers = 147456 B
#define NTHREADS 512

// ---------------- device scratch ----------------
__device__ float g_xin[(size_t)T_STEPS * B * NH];   // x @ x2h, [t*B+b][n]
__device__ float g_Whi[(size_t)NH * NH];            // h2h^T tf32-hi, [n][k]
__device__ float g_Wlo[(size_t)NH * NH];            // h2h^T tf32-lo, [n][k]
__device__ float g_Ahi[2][(size_t)B * NH];          // hy tf32-hi, [b][k], ping-pong
__device__ float g_Alo[2][(size_t)B * NH];          // hy tf32-lo
__device__ float g_hz[(size_t)B * PORT];            // hz state [b][j]
__device__ float g_part[(size_t)SPLITK * B * NH];   // split-K partials [kb][b][n]
__device__ int   g_cnt[NTILES];                     // arrival counters (self-reset)

// ---------------- helpers ----------------
__device__ __forceinline__ uint32_t smem_u32(const void* p) {
    uint32_t a;
    asm("{ .reg .u64 t; cvta.to.shared.u64 t, %1; cvt.u32.u64 %0, t; }" : "=r"(a) : "l"(p));
    return a;
}
__device__ __forceinline__ float tf32r(float x) {
    uint32_t u;
    asm("cvt.rna.tf32.f32 %0, %1;" : "=r"(u) : "f"(x));
    return __uint_as_float(u);
}
__device__ __forceinline__ void cpa16(uint32_t dst, const void* src) {
    asm volatile("cp.async.ca.shared.global [%0], [%1], 16;" :: "r"(dst), "l"(src));
}
#define CP_COMMIT() asm volatile("cp.async.commit_group;" ::: "memory")
#define CP_WAIT(n)  asm volatile("cp.async.wait_group %0;" :: "n"(n) : "memory")

__device__ __forceinline__ void mma_tf32(float* c, const uint32_t* a, const uint32_t* b) {
    asm volatile(
        "mma.sync.aligned.m16n8k8.row.col.f32.tf32.tf32.f32 "
        "{%0,%1,%2,%3}, {%4,%5,%6,%7}, {%8,%9}, {%0,%1,%2,%3};"
        : "+f"(c[0]), "+f"(c[1]), "+f"(c[2]), "+f"(c[3])
        : "r"(a[0]), "r"(a[1]), "r"(a[2]), "r"(a[3]), "r"(b[0]), "r"(b[1]));
}

// ---------------- init ----------------
__global__ void init_kernel() {
    int i = blockIdx.x * blockDim.x + threadIdx.x;
    if (i < B * NH) { g_Ahi[0][i] = 0.0f; g_Alo[0][i] = 0.0f; }
    if (i < B * PORT) g_hz[i] = 0.0f;
}

// ---------------- h2h -> transposed tf32 hi/lo split (one-time) --------------
__global__ void prep_kernel(const float* __restrict__ h2h) {
    __shared__ float s[32][33];
    int k = blockIdx.y * 32 + threadIdx.y;
    int n = blockIdx.x * 32 + threadIdx.x;
    s[threadIdx.y][threadIdx.x] = h2h[(size_t)k * NH + n];
    __syncthreads();
    int n2 = blockIdx.x * 32 + threadIdx.y;
    int k2 = blockIdx.y * 32 + threadIdx.x;
    float v = s[threadIdx.x][threadIdx.y];
    float hi = tf32r(v);
    g_Whi[(size_t)n2 * NH + k2] = hi;
    g_Wlo[(size_t)n2 * NH + k2] = tf32r(v - hi);
}

// ---------------- xin = x @ x2h for all timesteps (one-time) -----------------
__global__ void xin_kernel(const float* __restrict__ x, const float* __restrict__ x2h) {
    __shared__ float sx[64][NI];
    const int tid = threadIdx.x;
    const int r0 = blockIdx.x * 64;
    const int n = blockIdx.y * 256 + tid;
    for (int s = tid; s < 64 * NI; s += 256) {
        int r = s >> 5, i = s & 31;
        int R = r0 + r;
        int tt = R >> 7, bb = R & 127;
        sx[r][i] = x[((size_t)bb * T_STEPS + tt) * NI + i];
    }
    __syncthreads();
    float acc[64];
#pragma unroll
    for (int r = 0; r < 64; r++) acc[r] = 0.0f;
#pragma unroll
    for (int i = 0; i < NI; i++) {
        float w = x2h[(size_t)i * NH + n];
#pragma unroll
        for (int r = 0; r < 64; r++) acc[r] = fmaf(sx[r][i], w, acc[r]);
    }
#pragma unroll
    for (int r = 0; r < 64; r++)
        g_xin[(size_t)(r0 + r) * NH + n] = acc[r];
}

// ---------------- one step: tf32 mma.sync split GEMM + fused epilogue --------
// 512 threads, warp grid 4x4, warp tile 32(M) x 32(N)
__global__ void __launch_bounds__(NTHREADS, 1) step_kernel(
    const float* __restrict__ gamma, const float* __restrict__ eps,
    float* __restrict__ out, int t, int src)
{
    extern __shared__ float sm[];
    __shared__ int s_last;

    const int tid = threadIdx.x;
    const int warp = tid >> 5, lane = tid & 31;
    const int warpM = warp >> 2, warpN = warp & 3;   // 4 x 4 warp grid
    const int ntile = blockIdx.x, kb = blockIdx.y;
    const int n0 = ntile * NT, k0 = kb * KSLICE;
    const int dst = src ^ 1;

    const float* __restrict__ Ahi = g_Ahi[src];
    const float* __restrict__ Alo = g_Alo[src];

    // ---- cp.async stage of one K-chunk into buf (c & 1) ----
    auto issue = [&](int c) {
        float* bb = sm + (c & 1) * 4 * TSZ;
        const int kc = k0 + c * KC;
        const float* srcs[4] = {
            Ahi + kc, Alo + kc,
            g_Whi + (size_t)n0 * NH + kc, g_Wlo + (size_t)n0 * NH + kc
        };
#pragma unroll
        for (int tile = 0; tile < 4; tile++) {
            const float* sg = srcs[tile];
            float* dt = bb + tile * TSZ;
#pragma unroll
            for (int i = 0; i < 2; i++) {
                int s = tid + i * NTHREADS;     // 1024 slots: 128 rows x 8 x 16B
                int row = s >> 3, u = s & 7;
                cpa16(smem_u32(dt + row * TSTRIDE + u * 4),
                      sg + (size_t)row * NH + u * 4);
            }
        }
    };

    float C[2][4][4];
#pragma unroll
    for (int mi = 0; mi < 2; mi++)
#pragma unroll
        for (int ni = 0; ni < 4; ni++)
#pragma unroll
            for (int q = 0; q < 4; q++) C[mi][ni][q] = 0.0f;

    const int r = lane >> 2, cc = lane & 3;

    issue(0); CP_COMMIT();
    for (int c = 0; c < 8; c++) {
        if (c < 7) { issue(c + 1); CP_COMMIT(); CP_WAIT(1); }
        else       { CP_WAIT(0); }
        __syncthreads();
        const float* bb   = sm + (c & 1) * 4 * TSZ;
        const float* sAhi = bb;
        const float* sAlo = bb + TSZ;
        const float* sWhi = bb + 2 * TSZ;
        const float* sWlo = bb + 3 * TSZ;

#pragma unroll
        for (int ks = 0; ks < 4; ks++) {
            const int kk = ks * 8;
            uint32_t a[2][4], bh[4][2], bl[4][2];
#pragma unroll
            for (int mi = 0; mi < 2; mi++) {
                int row = warpM * 32 + mi * 16 + r;
                a[mi][0] = __float_as_uint(sAhi[row * TSTRIDE + kk + cc]);
                a[mi][1] = __float_as_uint(sAhi[(row + 8) * TSTRIDE + kk + cc]);
                a[mi][2] = __float_as_uint(sAhi[row * TSTRIDE + kk + cc + 4]);
                a[mi][3] = __float_as_uint(sAhi[(row + 8) * TSTRIDE + kk + cc + 4]);
            }
#pragma unroll
            for (int ni = 0; ni < 4; ni++) {
                int col = warpN * 32 + ni * 8 + r;
                bh[ni][0] = __float_as_uint(sWhi[col * TSTRIDE + kk + cc]);
                bh[ni][1] = __float_as_uint(sWhi[col * TSTRIDE + kk + cc + 4]);
                bl[ni][0] = __float_as_uint(sWlo[col * TSTRIDE + kk + cc]);
                bl[ni][1] = __float_as_uint(sWlo[col * TSTRIDE + kk + cc + 4]);
            }
#pragma unroll
            for (int mi = 0; mi < 2; mi++)
#pragma unroll
                for (int ni = 0; ni < 4; ni++) {
                    mma_tf32(C[mi][ni], a[mi], bh[ni]);   // Ahi * Whi
                    mma_tf32(C[mi][ni], a[mi], bl[ni]);   // Ahi * Wlo
                }
            // Alo pass (reuse bh)
#pragma unroll
            for (int mi = 0; mi < 2; mi++) {
                int row = warpM * 32 + mi * 16 + r;
                a[mi][0] = __float_as_uint(sAlo[row * TSTRIDE + kk + cc]);
                a[mi][1] = __float_as_uint(sAlo[(row + 8) * TSTRIDE + kk + cc]);
                a[mi][2] = __float_as_uint(sAlo[row * TSTRIDE + kk + cc + 4]);
                a[mi][3] = __float_as_uint(sAlo[(row + 8) * TSTRIDE + kk + cc + 4]);
            }
#pragma unroll
            for (int mi = 0; mi < 2; mi++)
#pragma unroll
                for (int ni = 0; ni < 4; ni++)
                    mma_tf32(C[mi][ni], a[mi], bh[ni]);   // Alo * Whi
        }
        __syncthreads();
    }

    // ---- write split-K partials ----
#pragma unroll
    for (int mi = 0; mi < 2; mi++)
#pragma unroll
        for (int ni = 0; ni < 4; ni++) {
            int row = warpM * 32 + mi * 16 + r;
            int col = n0 + warpN * 32 + ni * 8 + cc * 2;
            float2 v0 = make_float2(C[mi][ni][0], C[mi][ni][1]);
            float2 v1 = make_float2(C[mi][ni][2], C[mi][ni][3]);
            *(float2*)&g_part[((size_t)kb * B + row) * NH + col]     = v0;
            *(float2*)&g_part[((size_t)kb * B + row + 8) * NH + col] = v1;
        }

    __threadfence();
    if (tid == 0) {
        int v = atomicAdd(&g_cnt[ntile], 1);
        s_last = (v == SPLITK - 1);
    }
    __syncthreads();
    if (!s_last) return;
    if (tid == 0) g_cnt[ntile] = 0;

    // ---- fused epilogue (last CTA of this n-tile): 128 b x 128 n ------------
    const int n4 = n0 + lane * 4;
    const bool harm = (n0 < PORT);

    float4 gm = make_float4(0, 0, 0, 0), ep = make_float4(0, 0, 0, 0);
    if (harm) { gm = *(const float4*)&gamma[n4]; ep = *(const float4*)&eps[n4]; }

    float* out_hy  = out;
    float* out_hz  = out + (size_t)T_STEPS * B * NH;
    float* out_hyu = out_hz + (size_t)T_STEPS * B * PORT;
    float* out_spk = out_hyu + (size_t)T_STEPS * B * PORT;
    float* hyhi_d = g_Ahi[dst];
    float* hylo_d = g_Alo[dst];
    const float* old_hy = out_hy + (size_t)(t - 1) * B * NH;

    for (int rr = 0; rr < 8; rr++) {
        int b = rr * 16 + warp;
        const size_t ob = (size_t)t * B + b;

        float4 pre = make_float4(0, 0, 0, 0);
#pragma unroll
        for (int q = 0; q < SPLITK; q++) {
            float4 pv = *(const float4*)&g_part[((size_t)q * B + b) * NH + n4];
            pre.x += pv.x; pre.y += pv.y; pre.z += pv.z; pre.w += pv.w;
        }
        float4 xv = *(const float4*)&g_xin[((size_t)t * B + b) * NH + n4];
        pre.x += xv.x; pre.y += xv.y; pre.z += xv.z; pre.w += xv.w;

        float4 f;
        f.x = tanhf(pre.x); f.y = tanhf(pre.y);
        f.z = tanhf(pre.z); f.w = tanhf(pre.w);

        float4 old = make_float4(0, 0, 0, 0);
        if (t > 0) old = *(const float4*)&old_hy[(size_t)b * NH + n4];

        float4 newv;
        if (harm) {
            float4 hzo = *(const float4*)&g_hz[(size_t)b * PORT + n4];
            float4 hzn;
            hzn.x = hzo.x + DT * (f.x - gm.x * old.x - ep.x * hzo.x);
            hzn.y = hzo.y + DT * (f.y - gm.y * old.y - ep.y * hzo.y);
            hzn.z = hzo.z + DT * (f.z - gm.z * old.z - ep.z * hzo.z);
            hzn.w = hzo.w + DT * (f.w - gm.w * old.w - ep.w * hzo.w);
            newv.x = old.x + DT * hzn.x;
            newv.y = old.y + DT * hzn.y;
            newv.z = old.z + DT * hzn.z;
            newv.w = old.w + DT * hzn.w;
            *(float4*)&out_hy[ob * NH + n4]   = newv;
            *(float4*)&out_hz[ob * PORT + n4] = hzn;
            *(float4*)&g_hz[(size_t)b * PORT + n4] = hzn;
        } else {
            int j4 = n4 - PORT;
            float4 spk, u;
            spk.x = (old.x > THRESH) ? 1.0f : 0.0f;
            spk.y = (old.y > THRESH) ? 1.0f : 0.0f;
            spk.z = (old.z > THRESH) ? 1.0f : 0.0f;
            spk.w = (old.w > THRESH) ? 1.0f : 0.0f;
            u.x = (spk.x > 0.0f) ? 0.0f : old.x;
            u.y = (spk.y > 0.0f) ? 0.0f : old.y;
            u.z = (spk.z > 0.0f) ? 0.0f : old.z;
            u.w = (spk.w > 0.0f) ? 0.0f : old.w;
            newv.x = u.x + DT * (f.x - u.x);
            newv.y = u.y + DT * (f.y - u.y);
            newv.z = u.z + DT * (f.z - u.z);
            newv.w = u.w + DT * (f.w - u.w);
            *(float4*)&out_hy[ob * NH + n4]    = newv;
            *(float4*)&out_hyu[ob * PORT + j4] = newv;
            *(float4*)&out_spk[ob * PORT + j4] = spk;
        }
        // tf32 hi/lo split of new state for next step's GEMM (A row-major [b][k])
        float4 hi4, lo4;
        hi4.x = tf32r(newv.x); lo4.x = tf32r(newv.x - hi4.x);
        hi4.y = tf32r(newv.y); lo4.y = tf32r(newv.y - hi4.y);
        hi4.z = tf32r(newv.z); lo4.z = tf32r(newv.z - hi4.z);
        hi4.w = tf32r(newv.w); lo4.w = tf32r(newv.w - hi4.w);
        *(float4*)&hyhi_d[(size_t)b * NH + n4] = hi4;
        *(float4*)&hylo_d[(size_t)b * NH + n4] = lo4;
    }
}

// ---------------- launch ------------------------------------------------------
extern "C" void kernel_launch(void* const* d_in, const int* in_sizes, int n_in,
                              void* d_out, int out_size) {
    (void)in_sizes; (void)n_in; (void)out_size;
    const float* x     = (const float*)d_in[0];
    const float* x2h   = (const float*)d_in[1];
    const float* h2h   = (const float*)d_in[2];
    const float* gamma = (const float*)d_in[3];
    const float* eps   = (const float*)d_in[4];
    float* out = (float*)d_out;

    cudaFuncSetAttribute(step_kernel, cudaFuncAttributeMaxDynamicSharedMemorySize, SMEM_BYTES);

    init_kernel<<<256, 1024>>>();
    prep_kernel<<<dim3(NH / 32, NH / 32), dim3(32, 32)>>>(h2h);
    xin_kernel<<<dim3((T_STEPS * B) / 64, NH / 256), 256>>>(x, x2h);
    for (int t = 0; t < T_STEPS; t++)
        step_kernel<<<dim3(NTILES, SPLITK), NTHREADS, SMEM_BYTES>>>(gamma, eps, out, t, t & 1);
}